// round 6
// baseline (speedup 1.0000x reference)
#include <cuda_runtime.h>

// ---------------------------------------------------------------------------
// Single-sequence (batch row 255) 2-layer LSTM.
// Tagged (tick,value) u64 pairs; round 6: warp0-only sentinel discovery +
// one-shot LDG.128 staging (cuts per-CTA LSU poll issue from ~1000 LDG/round
// to ~32, staging loads halved and issued once).
// ---------------------------------------------------------------------------

#define HT   512
#define NA   32
#define NBG  64
#define NBLK 96
#define NTHR 256
#define R1   16   // h1 ring depth (A->B skew covered by backpressure)
#define R2   4    // h2 ring depth (B-B skew <= 1)
#define RO   4    // o  ring depth

typedef unsigned long long u64;

__device__ __align__(16) u64 g_h1p[R1][HT];
__device__ __align__(16) u64 g_h2p[R2][HT];
__device__ __align__(16) u64 g_op[RO][NBG];
__device__ int g_prog[NBG * 32];      // B progress flags, 128B padded

__device__ __forceinline__ float sigf(float v)   { return 1.0f / (1.0f + __expf(-v)); }
__device__ __forceinline__ float tanhff(float v) { return 2.0f / (1.0f + __expf(-2.0f * v)) - 1.0f; }

__device__ __forceinline__ u64 ldp(const u64* p) {
    u64 v; asm volatile("ld.relaxed.gpu.global.b64 %0, [%1];" : "=l"(v) : "l"(p) : "memory"); return v;
}
__device__ __forceinline__ void stp(u64* p, u64 v) {
    asm volatile("st.relaxed.gpu.global.b64 [%0], %1;" :: "l"(p), "l"(v) : "memory");
}
__device__ __forceinline__ void ldp2(const u64* p, u64& a, u64& b) {
    asm volatile("ld.volatile.global.v2.b64 {%0,%1}, [%2];"
                 : "=l"(a), "=l"(b) : "l"(p) : "memory");
}
__device__ __forceinline__ int ldacq(const int* p) {
    int v; asm volatile("ld.acquire.gpu.global.b32 %0, [%1];" : "=r"(v) : "l"(p) : "memory"); return v;
}
__device__ __forceinline__ void strel(int* p, int v) {
    asm volatile("st.release.gpu.global.b32 [%0], %1;" :: "l"(p), "r"(v) : "memory");
}
__device__ __forceinline__ u64 mkpair(float f, unsigned tag) {
    return ((u64)tag << 32) | (u64)__float_as_uint(f);
}
__device__ __forceinline__ float pval(u64 v) { return __uint_as_float((unsigned)v); }
__device__ __forceinline__ unsigned ptag(u64 v) { return (unsigned)(v >> 32); }

// packed fp32x2 fused multiply-add (Blackwell double-rate fp32 pipe)
__device__ __forceinline__ u64 fma2(u64 a, u64 b, u64 c) {
    u64 d;
    asm("fma.rn.f32x2 %0, %1, %2, %3;" : "=l"(d) : "l"(a), "l"(b), "l"(c));
    return d;
}
__device__ __forceinline__ float hsum2(u64 a) {
    return __uint_as_float((unsigned)a) + __uint_as_float((unsigned)(a >> 32));
}

__global__ void init_state_kernel() {
    int tid = threadIdx.x;
    for (int i = tid; i < R1 * HT;  i += NTHR) ((u64*)g_h1p)[i] = 0ull;  // tag 0, val 0
    for (int i = tid; i < R2 * HT;  i += NTHR) ((u64*)g_h2p)[i] = 0ull;
    for (int i = tid; i < RO * NBG; i += NTHR) ((u64*)g_op)[i]  = 0ull;
    for (int i = tid; i < NBG * 32; i += NTHR) g_prog[i] = 0;
}

__global__ void __launch_bounds__(NTHR, 1) lstm_sent_kernel(
    const float* __restrict__ input,
    const float* __restrict__ Wih1, const float* __restrict__ Whh1,
    const float* __restrict__ bih1, const float* __restrict__ bhh1,
    const float* __restrict__ Wih2, const float* __restrict__ Whh2,
    const float* __restrict__ bih2, const float* __restrict__ bhh2,
    const float* __restrict__ Wlin, const float* __restrict__ blin,
    float* __restrict__ out, int T, int pred_len, int Brows)
{
    __shared__ __align__(16) float sh1[HT];
    __shared__ __align__(16) float sh2[HT];
    __shared__ float sg[64];
    __shared__ float sb[64];
    __shared__ float swx[64];
    __shared__ float swlin[8];
    __shared__ float sxs;
    __shared__ float sxin[1024];

    const int tid  = threadIdx.x;
    const int wid  = tid >> 5;
    const int lane = tid & 31;
    const int total = T + pred_len - 1;

    if (blockIdx.x < NA) {
        // ===================== GROUP A : layer 1 =====================
        const int bA = blockIdx.x * 16;
        u64 wA2[8][8];   // 8 rows x 8 f32x2 pairs (K=512 over 32 lanes)
        #pragma unroll
        for (int rr = 0; rr < 8; ++rr) {
            int r = wid * 8 + rr;
            int R = ((r >> 4) << 9) + bA + (r & 15);
            const u64* Wr2 = (const u64*)(Whh1 + (size_t)R * HT);
            #pragma unroll
            for (int p = 0; p < 8; ++p) wA2[rr][p] = Wr2[lane + 32 * p];
        }
        if (tid < 64) {
            int r = tid;
            int R = ((r >> 4) << 9) + bA + (r & 15);
            sb[r]  = bih1[R] + bhh1[R];
            swx[r] = Wih1[R];
        }
        const float* xin = input + (size_t)(Brows - 1) * T;
        for (int i = tid; i < T && i < 1024; i += NTHR) sxin[i] = xin[i];
        const float blin0 = blin[0];
        float c1 = 0.f;
        __syncthreads();

        for (int t = 0; t < total; ++t) {
            // ---- warp0: backpressure (rare) + decode x poll + sentinel poll ----
            if (wid == 0) {
                if ((t & 7) == 0 && t >= 16) {
                    int need = t - 8;
                    const int* pp0 = &g_prog[lane * 32];
                    const int* pp1 = &g_prog[(lane + 32) * 32];
                    for (;;) {
                        bool ok = (ldacq(pp0) >= need) && (ldacq(pp1) >= need);
                        if (__ballot_sync(0xffffffffu, ok) == 0xffffffffu) break;
                    }
                }
                if (t >= T) {
                    const u64* q0 = &g_op[t & (RO - 1)][lane];
                    const u64* q1 = q0 + 32;
                    u64 a0, a1;
                    for (;;) {
                        a0 = ldp(q0); a1 = ldp(q1);
                        bool ok = (ptag(a0) == (unsigned)t) && (ptag(a1) == (unsigned)t);
                        if (__ballot_sync(0xffffffffu, ok) == 0xffffffffu) break;
                    }
                    float ov = pval(a0) + pval(a1);
                    #pragma unroll
                    for (int o = 16; o; o >>= 1) ov += __shfl_xor_sync(0xffffffffu, ov, o);
                    if (lane == 0) {
                        float xv = ov + blin0;
                        sxs = xv;
                        if (blockIdx.x == 0) out[t - T] = xv;
                    }
                }
                // sentinel: one element per A-producer chunk (16 u64 = 1 line)
                const u64* sp = &g_h1p[t & (R1 - 1)][lane * 16];
                for (;;) {
                    u64 v = ldp(sp);
                    if (__ballot_sync(0xffffffffu, ptag(v) == (unsigned)t) == 0xffffffffu) break;
                }
            }
            __syncthreads();

            // ---- one-shot vector staging (tags verified, retry ~never) ----
            {
                const u64* p = &g_h1p[t & (R1 - 1)][tid * 2];
                u64 a, b;
                ldp2(p, a, b);
                while (ptag(a) != (unsigned)t || ptag(b) != (unsigned)t) ldp2(p, a, b);
                ((float2*)sh1)[tid] = make_float2(pval(a), pval(b));
            }
            __syncthreads();

            // ---- gate matvec (packed f32x2) ----
            u64 hv2[8];
            #pragma unroll
            for (int p = 0; p < 8; ++p) hv2[p] = ((const u64*)sh1)[lane + 32 * p];
            #pragma unroll
            for (int rr = 0; rr < 8; ++rr) {
                u64 acc = 0ull;
                #pragma unroll
                for (int p = 0; p < 8; ++p) acc = fma2(wA2[rr][p], hv2[p], acc);
                float a = hsum2(acc);
                #pragma unroll
                for (int o = 16; o; o >>= 1) a += __shfl_xor_sync(0xffffffffu, a, o);
                if (lane == 0) sg[wid * 8 + rr] = a;
            }
            __syncthreads();

            // ---- activation + publish h1(t) tagged t+1 ----
            if (wid == 0) {
                const float x = (t < T) ? ((t < 1024) ? sxin[t] : __ldg(&xin[t])) : sxs;
                float v0 = sg[lane]      + sb[lane]      + x * swx[lane];
                float v1 = sg[lane + 32] + sb[lane + 32] + x * swx[lane + 32];
                float a0 = sigf(v0);                              // gates i, f
                float a1 = (lane < 16) ? tanhff(v1) : sigf(v1);   // gates g, o
                int u = lane & 15;
                float i_ = __shfl_sync(0xffffffffu, a0, u);
                float f_ = __shfl_sync(0xffffffffu, a0, u + 16);
                float g_ = __shfl_sync(0xffffffffu, a1, u);
                float o_ = __shfl_sync(0xffffffffu, a1, u + 16);
                if (lane < 16) {
                    c1 = f_ * c1 + i_ * g_;
                    float hh = o_ * tanhff(c1);
                    stp(&g_h1p[(t + 1) & (R1 - 1)][bA + lane], mkpair(hh, (unsigned)(t + 1)));
                }
            }
        }

        // ---- epilogue: o(total-1) tagged 'total' -> out[pred_len-1] ----
        if (blockIdx.x == 0 && wid == 0) {
            const u64* q0 = &g_op[total & (RO - 1)][lane];
            const u64* q1 = q0 + 32;
            u64 a0, a1;
            for (;;) {
                a0 = ldp(q0); a1 = ldp(q1);
                bool ok = (ptag(a0) == (unsigned)total) && (ptag(a1) == (unsigned)total);
                if (__ballot_sync(0xffffffffu, ok) == 0xffffffffu) break;
            }
            float ov = pval(a0) + pval(a1);
            #pragma unroll
            for (int o = 16; o; o >>= 1) ov += __shfl_xor_sync(0xffffffffu, ov, o);
            if (lane == 0) out[pred_len - 1] = ov + blin0;
        }
    } else {
        // ===================== GROUP B : layer 2 =====================
        const int jB = blockIdx.x - NA;
        const int bB = jB * 8;
        u64 wB2[4][16];  // 4 rows x 16 f32x2 pairs (K=1024 over 32 lanes)
        #pragma unroll
        for (int rr = 0; rr < 4; ++rr) {
            int r = wid * 4 + rr;
            int R = ((r >> 3) << 9) + bB + (r & 7);
            const u64* Wi2 = (const u64*)(Wih2 + (size_t)R * HT);
            const u64* Wh2 = (const u64*)(Whh2 + (size_t)R * HT);
            #pragma unroll
            for (int p = 0; p < 8; ++p) {
                wB2[rr][p]     = Wi2[lane + 32 * p];
                wB2[rr][8 + p] = Wh2[lane + 32 * p];
            }
        }
        if (tid < 32) {
            int r = tid;
            int R = ((r >> 3) << 9) + bB + (r & 7);
            sb[r] = bih2[R] + bhh2[R];
        }
        if (tid < 8) swlin[tid] = Wlin[bB + tid];
        float c2 = 0.f;
        __syncthreads();

        for (int k = 0; k < total; ++k) {
            // ---- warp0 sentinel poll: h1 tag k+1 (32 lines), h2 tag k (64 chunks) ----
            if (wid == 0) {
                const u64* s1  = &g_h1p[(k + 1) & (R1 - 1)][lane * 16];
                const u64* s2a = &g_h2p[k & (R2 - 1)][lane * 8];
                const u64* s2b = &g_h2p[k & (R2 - 1)][(lane + 32) * 8];
                for (;;) {
                    bool ok = (ptag(ldp(s1))  == (unsigned)(k + 1))
                           && (ptag(ldp(s2a)) == (unsigned)k)
                           && (ptag(ldp(s2b)) == (unsigned)k);
                    if (__ballot_sync(0xffffffffu, ok) == 0xffffffffu) break;
                }
            }
            __syncthreads();

            // ---- one-shot vector staging ----
            {
                const u64* p = &g_h1p[(k + 1) & (R1 - 1)][tid * 2];
                const u64* q = &g_h2p[k & (R2 - 1)][tid * 2];
                u64 a, b, c, d;
                ldp2(p, a, b);
                ldp2(q, c, d);
                while (ptag(a) != (unsigned)(k + 1) || ptag(b) != (unsigned)(k + 1)) ldp2(p, a, b);
                while (ptag(c) != (unsigned)k       || ptag(d) != (unsigned)k)       ldp2(q, c, d);
                ((float2*)sh1)[tid] = make_float2(pval(a), pval(b));
                ((float2*)sh2)[tid] = make_float2(pval(c), pval(d));
            }
            __syncthreads();
            if (tid == 0) strel(&g_prog[jB * 32], k);   // staging done

            // ---- gate matvec (K = 1024, packed f32x2) ----
            u64 hv2[16];
            #pragma unroll
            for (int p = 0; p < 8; ++p) {
                hv2[p]     = ((const u64*)sh1)[lane + 32 * p];
                hv2[8 + p] = ((const u64*)sh2)[lane + 32 * p];
            }
            #pragma unroll
            for (int rr = 0; rr < 4; ++rr) {
                u64 acc = 0ull;
                #pragma unroll
                for (int p = 0; p < 16; ++p) acc = fma2(wB2[rr][p], hv2[p], acc);
                float a = hsum2(acc);
                #pragma unroll
                for (int o = 16; o; o >>= 1) a += __shfl_xor_sync(0xffffffffu, a, o);
                if (lane == 0) sg[wid * 4 + rr] = a;
            }
            __syncthreads();

            // ---- activation + publish h2(k) tag k+1, o partial tag k+1 ----
            if (wid == 0) {
                float v = sg[lane] + sb[lane];
                float a = ((lane >> 3) == 2) ? tanhff(v) : sigf(v);
                int u = lane & 7;
                float i_ = __shfl_sync(0xffffffffu, a, u);
                float f_ = __shfl_sync(0xffffffffu, a, u + 8);
                float g_ = __shfl_sync(0xffffffffu, a, u + 16);
                float o_ = __shfl_sync(0xffffffffu, a, u + 24);
                float p = 0.f;
                if (lane < 8) {
                    c2 = f_ * c2 + i_ * g_;
                    float hh = o_ * tanhff(c2);
                    stp(&g_h2p[(k + 1) & (R2 - 1)][bB + lane], mkpair(hh, (unsigned)(k + 1)));
                    p = swlin[lane] * hh;
                }
                p += __shfl_xor_sync(0xffffffffu, p, 4);
                p += __shfl_xor_sync(0xffffffffu, p, 2);
                p += __shfl_xor_sync(0xffffffffu, p, 1);
                if (lane == 0 && k >= T - 1)
                    stp(&g_op[(k + 1) & (RO - 1)][jB], mkpair(p, (unsigned)(k + 1)));
            }
        }
    }
}

extern "C" void kernel_launch(void* const* d_in, const int* in_sizes, int n_in,
                              void* d_out, int out_size) {
    int off = (n_in >= 12 && in_sizes[1] == 1) ? 2 : 1;

    const float* input = (const float*)d_in[0];
    const float* Wih1  = (const float*)d_in[off + 0];
    const float* Whh1  = (const float*)d_in[off + 1];
    const float* bih1  = (const float*)d_in[off + 2];
    const float* bhh1  = (const float*)d_in[off + 3];
    const float* Wih2  = (const float*)d_in[off + 4];
    const float* Whh2  = (const float*)d_in[off + 5];
    const float* bih2  = (const float*)d_in[off + 6];
    const float* bhh2  = (const float*)d_in[off + 7];
    const float* Wlin  = (const float*)d_in[off + 8];
    const float* blin  = (const float*)d_in[off + 9];

    const int B = 256;
    const int T = in_sizes[0] / B;
    const int pred_len = out_size;

    init_state_kernel<<<1, NTHR>>>();
    lstm_sent_kernel<<<NBLK, NTHR>>>(
        input, Wih1, Whh1, bih1, bhh1, Wih2, Whh2, bih2, bhh2, Wlin, blin,
        (float*)d_out, T, pred_len, B);
}

// round 7
// speedup vs baseline: 1.2969x; 1.2969x over previous
#include <cuda_runtime.h>

// ---------------------------------------------------------------------------
// Single-sequence (batch row 255) 2-layer LSTM — merged-layer dataflow.
//
// 64 persistent CTAs x 256 threads. CTA b owns units [b*8, b*8+8) of BOTH
// layers. At tick t each CTA computes h1(t) (from h1(t-1)) AND h2(t-1)
// (from h1(t-1), h2(t-2)) -> ONE tagged-pair exchange per tick, one serial
// chain. Consumption-coupling bounds cross-CTA skew <= 1 -> ring depth 4,
// no backpressure flags. Discovery = data load (tagged u64 pairs, R5-proven).
// Activations for l1/l2 run in parallel warps 0/1.
// ---------------------------------------------------------------------------

#define HT    512
#define NBLK  64
#define NTHR  256
#define RNG   4

typedef unsigned long long u64;

__device__ __align__(16) u64 g_h1p[RNG][HT];
__device__ __align__(16) u64 g_h2p[RNG][HT];
__device__ __align__(16) u64 g_op[RNG][NBLK];

__device__ __forceinline__ float sigf(float v)   { return 1.0f / (1.0f + __expf(-v)); }
__device__ __forceinline__ float tanhff(float v) { return 2.0f / (1.0f + __expf(-2.0f * v)) - 1.0f; }

__device__ __forceinline__ u64 ldp(const u64* p) {
    u64 v; asm volatile("ld.relaxed.gpu.global.b64 %0, [%1];" : "=l"(v) : "l"(p) : "memory"); return v;
}
__device__ __forceinline__ void stp(u64* p, u64 v) {
    asm volatile("st.relaxed.gpu.global.b64 [%0], %1;" :: "l"(p), "l"(v) : "memory");
}
__device__ __forceinline__ u64 mkpair(float f, unsigned tag) {
    return ((u64)tag << 32) | (u64)__float_as_uint(f);
}
__device__ __forceinline__ float pval(u64 v) { return __uint_as_float((unsigned)v); }
__device__ __forceinline__ unsigned ptag(u64 v) { return (unsigned)(v >> 32); }

__device__ __forceinline__ u64 fma2(u64 a, u64 b, u64 c) {
    u64 d;
    asm("fma.rn.f32x2 %0, %1, %2, %3;" : "=l"(d) : "l"(a), "l"(b), "l"(c));
    return d;
}
__device__ __forceinline__ float hsum2(u64 a) {
    return __uint_as_float((unsigned)a) + __uint_as_float((unsigned)(a >> 32));
}

__global__ void init_state_kernel() {
    int tid = threadIdx.x;
    for (int i = tid; i < RNG * HT;   i += NTHR) { ((u64*)g_h1p)[i] = 0ull; ((u64*)g_h2p)[i] = 0ull; }
    for (int i = tid; i < RNG * NBLK; i += NTHR) ((u64*)g_op)[i] = 0ull;
}

__global__ void __launch_bounds__(NTHR, 1) lstm_merged_kernel(
    const float* __restrict__ input,
    const float* __restrict__ Wih1, const float* __restrict__ Whh1,
    const float* __restrict__ bih1, const float* __restrict__ bhh1,
    const float* __restrict__ Wih2, const float* __restrict__ Whh2,
    const float* __restrict__ bih2, const float* __restrict__ bhh2,
    const float* __restrict__ Wlin, const float* __restrict__ blin,
    float* __restrict__ out, int T, int pred_len, int Brows)
{
    __shared__ __align__(16) float sh1[HT];
    __shared__ __align__(16) float sh2[HT];
    __shared__ float sgl1[32];
    __shared__ float sgl2[32];
    __shared__ float sbl1[32];
    __shared__ float sbl2[32];
    __shared__ float swx[32];
    __shared__ float swlin[8];
    __shared__ float sxin[1024];

    const int tid  = threadIdx.x;
    const int wid  = tid >> 5;      // 8 warps
    const int lane = tid & 31;
    const int b8   = blockIdx.x * 8;
    const int total = T + pred_len - 1;   // ticks run t = 0 .. total

    // ---- register-resident weights ----
    // warp w owns l1 rows [4w,4w+4) and l2 rows [4w,4w+4) (local row = gate*8+unit)
    u64 wl1[4][8];    // K=512  -> 8 u64 pairs per row per lane
    u64 wl2[4][16];   // K=1024 -> 16 pairs  [Wih2 | Whh2]
    #pragma unroll
    for (int rr = 0; rr < 4; ++rr) {
        int r = wid * 4 + rr;
        int R = ((r >> 3) << 9) + b8 + (r & 7);
        const u64* W1 = (const u64*)(Whh1 + (size_t)R * HT);
        const u64* Wi = (const u64*)(Wih2 + (size_t)R * HT);
        const u64* Wh = (const u64*)(Whh2 + (size_t)R * HT);
        #pragma unroll
        for (int p = 0; p < 8; ++p) {
            wl1[rr][p]     = W1[lane + 32 * p];
            wl2[rr][p]     = Wi[lane + 32 * p];
            wl2[rr][8 + p] = Wh[lane + 32 * p];
        }
    }
    if (tid < 32) {
        int r = tid;
        int R = ((r >> 3) << 9) + b8 + (r & 7);
        sbl1[r] = bih1[R] + bhh1[R];
        swx[r]  = Wih1[R];
        sbl2[r] = bih2[R] + bhh2[R];
    }
    if (tid < 8) swlin[tid] = Wlin[b8 + tid];
    const float* xin = input + (size_t)(Brows - 1) * T;
    for (int i = tid; i < T && i < 1024; i += NTHR) sxin[i] = xin[i];
    const float blin0 = blin[0];

    float c1 = 0.f;   // warp0 lanes<8
    float c2 = 0.f;   // warp1 lanes<8
    __syncthreads();

    for (int t = 0; t <= total; ++t) {
        const int slot = t & (RNG - 1);

        // ---- staging: discovery IS the data load (4 pairs/thread, pipelined) ----
        {
            const u64* p0 = &g_h1p[slot][tid];
            const u64* p1 = p0 + 256;
            const u64* q0 = &g_h2p[slot][tid];
            const u64* q1 = q0 + 256;
            u64 v0, v1, w0, w1;
            bool o0 = false, o1 = false, o2 = false, o3 = false;
            do {
                if (!o0) { v0 = ldp(p0); o0 = (ptag(v0) == (unsigned)t); }
                if (!o1) { v1 = ldp(p1); o1 = (ptag(v1) == (unsigned)t); }
                if (!o2) { w0 = ldp(q0); o2 = (ptag(w0) == (unsigned)t); }
                if (!o3) { w1 = ldp(q1); o3 = (ptag(w1) == (unsigned)t); }
            } while (!(o0 && o1 && o2 && o3));
            sh1[tid]       = pval(v0);
            sh1[tid + 256] = pval(v1);
            sh2[tid]       = pval(w0);
            sh2[tid + 256] = pval(w1);
        }
        __syncthreads();

        // ---- matvec: l1 (4 rows, K=512) + l2 (4 rows, K=1024) per warp ----
        {
            u64 hv1[8];
            #pragma unroll
            for (int p = 0; p < 8; ++p) hv1[p] = ((const u64*)sh1)[lane + 32 * p];
            #pragma unroll
            for (int rr = 0; rr < 4; ++rr) {
                u64 acc = 0ull;
                #pragma unroll
                for (int p = 0; p < 8; ++p) acc = fma2(wl1[rr][p], hv1[p], acc);
                float a = hsum2(acc);
                #pragma unroll
                for (int o = 16; o; o >>= 1) a += __shfl_xor_sync(0xffffffffu, a, o);
                if (lane == 0) sgl1[wid * 4 + rr] = a;
            }
            u64 hv2[8];
            #pragma unroll
            for (int p = 0; p < 8; ++p) hv2[p] = ((const u64*)sh2)[lane + 32 * p];
            #pragma unroll
            for (int rr = 0; rr < 4; ++rr) {
                u64 acc = 0ull;
                #pragma unroll
                for (int p = 0; p < 8; ++p) acc = fma2(wl2[rr][p], hv1[p], acc);
                #pragma unroll
                for (int p = 0; p < 8; ++p) acc = fma2(wl2[rr][8 + p], hv2[p], acc);
                float a = hsum2(acc);
                #pragma unroll
                for (int o = 16; o; o >>= 1) a += __shfl_xor_sync(0xffffffffu, a, o);
                if (lane == 0) sgl2[wid * 4 + rr] = a;
            }
        }
        __syncthreads();

        // ---- warp1: layer-2 activation -> h2(t-1), o-partial ----
        if (wid == 1) {
            float hh = 0.f;
            if (lane < 8) {
                float vi = sgl2[lane]      + sbl2[lane];
                float vf = sgl2[8 + lane]  + sbl2[8 + lane];
                float vg = sgl2[16 + lane] + sbl2[16 + lane];
                float vo = sgl2[24 + lane] + sbl2[24 + lane];
                float i_ = sigf(vi), f_ = sigf(vf), g_ = tanhff(vg), o_ = sigf(vo);
                c2 = f_ * c2 + i_ * g_;
                hh = o_ * tanhff(c2);
                stp(&g_h2p[(t + 1) & (RNG - 1)][b8 + lane], mkpair(hh, (unsigned)(t + 1)));
            }
            if (t >= T) {
                float p = (lane < 8) ? swlin[lane] * hh : 0.f;
                p += __shfl_xor_sync(0xffffffffu, p, 4);
                p += __shfl_xor_sync(0xffffffffu, p, 2);
                p += __shfl_xor_sync(0xffffffffu, p, 1);
                if (lane == 0)
                    stp(&g_op[slot][blockIdx.x], mkpair(p, (unsigned)t));
            }
        }

        // ---- warp0: x (encode smem / decode o-reduce) + layer-1 activation ----
        if (wid == 0) {
            float x;
            if (t < T) {
                x = sxin[t];
            } else {
                // gather o(t-1): 64 tagged partials, 2 per lane
                const u64* q0 = &g_op[slot][lane];
                const u64* q1 = q0 + 32;
                u64 a0, a1;
                bool d0 = false, d1 = false;
                do {
                    if (!d0) { a0 = ldp(q0); d0 = (ptag(a0) == (unsigned)t); }
                    if (!d1) { a1 = ldp(q1); d1 = (ptag(a1) == (unsigned)t); }
                } while (!(d0 && d1));
                float ov = pval(a0) + pval(a1);
                #pragma unroll
                for (int o = 16; o; o >>= 1) ov += __shfl_xor_sync(0xffffffffu, ov, o);
                x = ov + blin0;
                if (blockIdx.x == 0 && lane == 0) out[t - T] = x;
            }
            if (t < total && lane < 8) {
                float vi = sgl1[lane]      + sbl1[lane]      + x * swx[lane];
                float vf = sgl1[8 + lane]  + sbl1[8 + lane]  + x * swx[8 + lane];
                float vg = sgl1[16 + lane] + sbl1[16 + lane] + x * swx[16 + lane];
                float vo = sgl1[24 + lane] + sbl1[24 + lane] + x * swx[24 + lane];
                float i_ = sigf(vi), f_ = sigf(vf), g_ = tanhff(vg), o_ = sigf(vo);
                c1 = f_ * c1 + i_ * g_;
                float hh = o_ * tanhff(c1);
                stp(&g_h1p[(t + 1) & (RNG - 1)][b8 + lane], mkpair(hh, (unsigned)(t + 1)));
            }
        }
        // no sync needed: next staging spins on tags; smem WAR protected by syncs above
    }
}

extern "C" void kernel_launch(void* const* d_in, const int* in_sizes, int n_in,
                              void* d_out, int out_size) {
    int off = (n_in >= 12 && in_sizes[1] == 1) ? 2 : 1;

    const float* input = (const float*)d_in[0];
    const float* Wih1  = (const float*)d_in[off + 0];
    const float* Whh1  = (const float*)d_in[off + 1];
    const float* bih1  = (const float*)d_in[off + 2];
    const float* bhh1  = (const float*)d_in[off + 3];
    const float* Wih2  = (const float*)d_in[off + 4];
    const float* Whh2  = (const float*)d_in[off + 5];
    const float* bih2  = (const float*)d_in[off + 6];
    const float* bhh2  = (const float*)d_in[off + 7];
    const float* Wlin  = (const float*)d_in[off + 8];
    const float* blin  = (const float*)d_in[off + 9];

    const int B = 256;
    const int T = in_sizes[0] / B;
    const int pred_len = out_size;

    init_state_kernel<<<1, NTHR>>>();
    lstm_merged_kernel<<<NBLK, NTHR>>>(
        input, Wih1, Whh1, bih1, bhh1, Wih2, Whh2, bih2, bhh2, Wlin, blin,
        (float*)d_out, T, pred_len, B);
}